// round 17
// baseline (speedup 1.0000x reference)
#include <cuda_runtime.h>
#include <cuda_bf16.h>
#include <cstdint>

#define NN 50000
#define EE 600000
#define DH 128
#define DO 40
#define BN_EPS 1e-5f
#define SCAN_B 49   // ceil(NN/1024)
#define NPAD 50048  // padded rows
#define K2 64       // DH/2 packed bf16x2 per row

// ---------------- scratch (device globals; referenced by symbol only) -------
__device__ __align__(16) float    g_h [(size_t)NN * DO];     // gemm40 out (40-wide)
__device__ __align__(16) uint32_t g_hh[(size_t)NPAD * K2];   // gemm_tc out, bf16x2
__device__ __align__(16) uint32_t g_xh[(size_t)NPAD * K2];   // x as bf16x2 (hi only)
__device__ __align__(16) uint32_t g_ah[(size_t)NPAD * K2];   // agg out (hi)
__device__ __align__(16) uint32_t g_al[(size_t)NPAD * K2];   // agg out (lo, for gemm40)
__device__ __align__(16) uint32_t g_w0h[K2 * DH], g_w0l[K2 * DH];
__device__ __align__(16) uint32_t g_w1h[K2 * DH], g_w1l[K2 * DH];
__device__ int   g_cnt[NN];
__device__ int   g_start[NN + 1];
__device__ int   g_cursor[NN];
__device__ int   g_srcCSR[EE];
__device__ float g_dinv[NN];
__device__ int   g_is64;
__device__ int   g_bsum[SCAN_B];

__device__ __forceinline__ int load_idx(const void* ei, int pos) {
    if (g_is64) return (int)((const long long*)ei)[pos];
    return ((const int*)ei)[pos];
}

// ---------------- bf16 helpers ------------------------------------------------
__device__ __forceinline__ uint32_t bf16_split2(float x0, float x1, uint32_t& lo) {
    __nv_bfloat16 h0 = __float2bfloat16_rn(x0);
    __nv_bfloat16 h1 = __float2bfloat16_rn(x1);
    __nv_bfloat16 l0 = __float2bfloat16_rn(x0 - __bfloat162float(h0));
    __nv_bfloat16 l1 = __float2bfloat16_rn(x1 - __bfloat162float(h1));
    __nv_bfloat162 H = __halves2bfloat162(h0, h1);
    __nv_bfloat162 L = __halves2bfloat162(l0, l1);
    lo = *reinterpret_cast<uint32_t*>(&L);
    return *reinterpret_cast<uint32_t*>(&H);
}

__device__ __forceinline__ uint32_t bf16_pack2(float x0, float x1) {
    __nv_bfloat162 H = __halves2bfloat162(__float2bfloat16_rn(x0), __float2bfloat16_rn(x1));
    return *reinterpret_cast<uint32_t*>(&H);
}

__device__ __forceinline__ float2 bf16_unpack2(uint32_t h) {
    __nv_bfloat162 H = *reinterpret_cast<__nv_bfloat162*>(&h);
    return __bfloat1622float2(H);
}

__device__ __forceinline__ float2 unsplit2(uint32_t h, uint32_t l) {
    float2 fh = bf16_unpack2(h);
    float2 fl = bf16_unpack2(l);
    return make_float2(fh.x + fl.x, fh.y + fl.y);
}

__device__ __forceinline__ void mma_bf16(float* d, const uint32_t* a, const uint32_t* b) {
    asm volatile(
        "mma.sync.aligned.m16n8k16.row.col.f32.bf16.bf16.f32 "
        "{%0,%1,%2,%3}, {%4,%5,%6,%7}, {%8,%9}, {%0,%1,%2,%3};"
        : "+f"(d[0]), "+f"(d[1]), "+f"(d[2]), "+f"(d[3])
        : "r"(a[0]), "r"(a[1]), "r"(a[2]), "r"(a[3]), "r"(b[0]), "r"(b[1]));
}

// ---------------- fused pre-split kernel (x hi-only + W0/W1 hi+lo) ----------
__global__ void k_split(const float* __restrict__ x,
                        const float* __restrict__ W0, const float* __restrict__ W1) {
    int i = blockIdx.x * blockDim.x + threadIdx.x;
    size_t base = (size_t)i * 8;
    if (base < (size_t)NN * DH) {
        float4 v0 = *(const float4*)(x + base);
        float4 v1 = *(const float4*)(x + base + 4);
        uint4 hi;
        hi.x = bf16_pack2(v0.x, v0.y);
        hi.y = bf16_pack2(v0.z, v0.w);
        hi.z = bf16_pack2(v1.x, v1.y);
        hi.w = bf16_pack2(v1.z, v1.w);
        *(uint4*)(g_xh + base / 2) = hi;
    }
    if (i < 2 * K2 * DH) {
        int wi = i / (K2 * DH);
        int r  = i % (K2 * DH);
        int k2 = r / DH;
        int n  = r % DH;
        const float* W = wi ? W1 : W0;
        uint32_t lo;
        uint32_t hi = bf16_split2(W[(2 * k2) * DH + n], W[(2 * k2 + 1) * DH + n], lo);
        if (wi) { g_w1h[r] = hi; g_w1l[r] = lo; }
        else    { g_w0h[r] = hi; g_w0l[r] = lo; }
    }
}

// ---------------- zero counters + dtype detection (fused) -------------------
__global__ void k_zero(const int* __restrict__ w) {
    int i = blockIdx.x * blockDim.x + threadIdx.x;
    if (i < NN) g_cnt[i] = 0;
    if (i == 0) {
        int all0 = 1;
#pragma unroll
        for (int k = 1; k < 32; k += 2) all0 &= (w[k] == 0);
        g_is64 = all0;
    }
}

__global__ void k_count(const void* __restrict__ ei) {
    int e = blockIdx.x * blockDim.x + threadIdx.x;
    if (e < EE) {
        int t = load_idx(ei, EE + e);
        if ((unsigned)t < NN) atomicAdd(&g_cnt[t], 1);
    }
}

__global__ void k_scan1() {
    __shared__ int wsum[32];
    int tid  = threadIdx.x;
    int lane = tid & 31;
    int wid  = tid >> 5;
    int i = blockIdx.x * 1024 + tid;
    int c = (i < NN) ? g_cnt[i] : 0;
    int v = c;
#pragma unroll
    for (int off = 1; off < 32; off <<= 1) {
        int n = __shfl_up_sync(0xffffffffu, v, off);
        if (lane >= off) v += n;
    }
    if (lane == 31) wsum[wid] = v;
    __syncthreads();
    if (wid == 0) {
        int s = wsum[lane];
#pragma unroll
        for (int off = 1; off < 32; off <<= 1) {
            int n = __shfl_up_sync(0xffffffffu, s, off);
            if (lane >= off) s += n;
        }
        wsum[lane] = s;
    }
    __syncthreads();
    int incl = ((wid == 0) ? 0 : wsum[wid - 1]) + v;
    if (i < NN) g_start[i] = incl;
    if (tid == 1023) g_bsum[blockIdx.x] = incl;
}

__global__ void k_scan23() {
    __shared__ int s_off;
    int tid = threadIdx.x;
    int bq  = blockIdx.x >> 2;
    if (tid < 32) {
        int lane = tid;
        int v = (lane < bq) ? g_bsum[lane] : 0;
        if (lane + 32 < bq) v += g_bsum[lane + 32];
#pragma unroll
        for (int off = 16; off > 0; off >>= 1)
            v += __shfl_xor_sync(0xffffffffu, v, off);
        if (lane == 0) s_off = v;
    }
    __syncthreads();
    int boff = s_off;
    int i = blockIdx.x * blockDim.x + tid;
    if (i < NN) {
        int c    = g_cnt[i];
        int excl = g_start[i] - c + boff;
        g_start[i]  = excl;
        g_cursor[i] = excl;
        g_dinv[i]   = rsqrtf((float)(c + 1));
    }
    if (blockIdx.x == 0 && tid == 0) g_start[NN] = EE;
}

__global__ void k_fill(const void* __restrict__ ei) {
    int e = blockIdx.x * blockDim.x + threadIdx.x;
    if (e < EE) {
        int s = load_idx(ei, e);
        int t = load_idx(ei, EE + e);
        if ((unsigned)s < NN && (unsigned)t < NN) {
            int p = atomicAdd(&g_cursor[t], 1);
            g_srcCSR[p] = s;
        }
    }
}

// ---------------- GEMM (OUTC=128) via bf16 TC, 2-term (X bf16, W hi+lo) -----
template <int LAYER>
__global__ void __launch_bounds__(256, 2) k_gemm_tc(const float* __restrict__ B) {
    const uint32_t* __restrict__ XH = LAYER ? g_ah : g_xh;
    const uint32_t* __restrict__ WH = LAYER ? g_w1h : g_w0h;
    const uint32_t* __restrict__ WL = LAYER ? g_w1l : g_w0l;
    __shared__ uint32_t Xh[128][20];
    __shared__ uint32_t Wh[16][136], Wl[16][136];
    int tid  = threadIdx.x;
    int wid  = tid >> 5;
    int lane = tid & 31;
    int l4   = lane & 3;
    int lq   = lane >> 2;
    int wr0  = (wid & 3) * 32;
    int wc0  = (wid >> 2) * 64;
    int row0 = blockIdx.x * 128;

    float acc[2][8][4];
#pragma unroll
    for (int m = 0; m < 2; m++)
#pragma unroll
        for (int n = 0; n < 8; n++)
#pragma unroll
            for (int q = 0; q < 4; q++) acc[m][n][q] = 0.f;

    for (int kb = 0; kb < K2; kb += 16) {
#pragma unroll
        for (int l = tid; l < 512; l += 256) {
            int r = l >> 2;
            int q = (l & 3) * 4;
            size_t gi = (size_t)(row0 + r) * K2 + kb + q;
            *(uint4*)&Xh[r][q] = *(const uint4*)(XH + gi);
        }
#pragma unroll
        for (int l = tid; l < 512; l += 256) {
            int r2 = l >> 5;
            int c  = (l & 31) * 4;
            size_t gi = (size_t)(kb + r2) * DH + c;
            *(uint4*)&Wh[r2][c] = *(const uint4*)(WH + gi);
            *(uint4*)&Wl[r2][c] = *(const uint4*)(WL + gi);
        }
        __syncthreads();

#pragma unroll
        for (int kb2 = 0; kb2 < 16; kb2 += 8) {
            uint32_t Ah[2][4];
#pragma unroll
            for (int m = 0; m < 2; m++) {
                int rb = wr0 + m * 16;
                Ah[m][0] = Xh[rb + lq][kb2 + l4];
                Ah[m][1] = Xh[rb + lq + 8][kb2 + l4];
                Ah[m][2] = Xh[rb + lq][kb2 + l4 + 4];
                Ah[m][3] = Xh[rb + lq + 8][kb2 + l4 + 4];
            }
#pragma unroll
            for (int nf = 0; nf < 8; nf++) {
                int cb = wc0 + nf * 8 + lq;
                uint32_t Bh[2], Bl[2];
                Bh[0] = Wh[kb2 + l4][cb];
                Bh[1] = Wh[kb2 + l4 + 4][cb];
                Bl[0] = Wl[kb2 + l4][cb];
                Bl[1] = Wl[kb2 + l4 + 4][cb];
                mma_bf16(acc[0][nf], Ah[0], Bh);
                mma_bf16(acc[1][nf], Ah[1], Bh);
                mma_bf16(acc[0][nf], Ah[0], Bl);
                mma_bf16(acc[1][nf], Ah[1], Bl);
            }
        }
        __syncthreads();
    }

#pragma unroll
    for (int nf = 0; nf < 8; nf++) {
        int col = wc0 + nf * 8 + 2 * l4;
        float2 bb = *(const float2*)(B + col);
        int k2i = col >> 1;
#pragma unroll
        for (int m = 0; m < 2; m++) {
            int rb = row0 + wr0 + m * 16 + lq;
            if (rb < NN)
                g_hh[(size_t)rb * K2 + k2i] =
                    bf16_pack2(acc[m][nf][0] + bb.x, acc[m][nf][1] + bb.y);
            if (rb + 8 < NN)
                g_hh[(size_t)(rb + 8) * K2 + k2i] =
                    bf16_pack2(acc[m][nf][2] + bb.x, acc[m][nf][3] + bb.y);
        }
    }
}

// ---------------- GEMM (OUTC=40): reads split agg output, fp32 math ---------
__global__ void __launch_bounds__(160) k_gemm40(const float* __restrict__ W,
                                                const float* __restrict__ B) {
    __shared__ __align__(16) float Xs[32][132];
    __shared__ __align__(16) float Ws[32][44];
    int tid = threadIdx.x;
    int tx  = tid % 10;
    int ty  = tid / 10;
    int row0 = blockIdx.x * 128;

    float acc[8][4];
#pragma unroll
    for (int i = 0; i < 8; i++)
#pragma unroll
        for (int j = 0; j < 4; j++) acc[i][j] = 0.f;

    for (int k0 = 0; k0 < DH; k0 += 32) {
        int k2b = k0 / 2;
        for (int l = tid; l < 1024; l += 160) {
            int r  = l >> 3;
            int c4 = l & 7;
            size_t gi = (size_t)(row0 + r) * K2 + k2b + c4 * 2;
            uint2 hh = *(const uint2*)(g_ah + gi);
            uint2 ll = *(const uint2*)(g_al + gi);
            float2 f0 = unsplit2(hh.x, ll.x);
            float2 f1 = unsplit2(hh.y, ll.y);
            Xs[c4 * 4 + 0][r] = f0.x;
            Xs[c4 * 4 + 1][r] = f0.y;
            Xs[c4 * 4 + 2][r] = f1.x;
            Xs[c4 * 4 + 3][r] = f1.y;
        }
        for (int l = tid; l < 320; l += 160) {
            int r = l / 10;
            int c = (l % 10) * 4;
            float4 v = *(const float4*)(W + (size_t)(k0 + r) * DO + c);
            *(float4*)&Ws[r][c] = v;
        }
        __syncthreads();
#pragma unroll
        for (int kk = 0; kk < 32; kk++) {
            float4 x0 = *(const float4*)&Xs[kk][ty * 8];
            float4 x1 = *(const float4*)&Xs[kk][ty * 8 + 4];
            float4 w0 = *(const float4*)&Ws[kk][tx * 4];
            float xv[8] = {x0.x, x0.y, x0.z, x0.w, x1.x, x1.y, x1.z, x1.w};
            float wv[4] = {w0.x, w0.y, w0.z, w0.w};
#pragma unroll
            for (int i = 0; i < 8; i++)
#pragma unroll
                for (int j = 0; j < 4; j++) acc[i][j] += xv[i] * wv[j];
        }
        __syncthreads();
    }

    float4 B0 = *(const float4*)(B + tx * 4);
#pragma unroll
    for (int i = 0; i < 8; i++) {
        int r = row0 + ty * 8 + i;
        if (r >= NN) continue;
        float4 o;
        o.x = acc[i][0] + B0.x;
        o.y = acc[i][1] + B0.y;
        o.z = acc[i][2] + B0.z;
        o.w = acc[i][3] + B0.w;
        *(float4*)(g_h + (size_t)r * DO + tx * 4) = o;
    }
}

// -------- aggregation over bf16-packed h + fused BN + ReLU ------------------
// Edge indices batch-prefetched 32 at a time (one per lane), broadcast via
// shfl: gathers become address-ready (MLP up to 32 vs 1 on the old
// index-load->gather chain).
__global__ void k_agg128(const float* __restrict__ gg, const float* __restrict__ be,
                         const float* __restrict__ mm, const float* __restrict__ vv) {
    int w    = (blockIdx.x * blockDim.x + threadIdx.x) >> 5;
    int lane = threadIdx.x & 31;
    if (w >= NN) return;
    float di = g_dinv[w];
    float sn = di * di;
    size_t ri = (size_t)w * K2 + lane * 2;
    uint2 hv = *(const uint2*)(g_hh + ri);
    float2 s0 = bf16_unpack2(hv.x);
    float2 s1 = bf16_unpack2(hv.y);
    float4 acc = make_float4(s0.x * sn, s0.y * sn, s1.x * sn, s1.y * sn);
    int e0 = g_start[w], e1 = g_start[w + 1];
    for (int eb = e0; eb < e1; eb += 32) {
        int n = e1 - eb;
        if (n > 32) n = 32;
        int   si = 0;
        float dv = 0.f;
        if (lane < n) {
            si = g_srcCSR[eb + lane];
            dv = g_dinv[si];
        }
        for (int j = 0; j < n; j++) {
            int   s  = __shfl_sync(0xffffffffu, si, j);
            float nw = __shfl_sync(0xffffffffu, dv, j) * di;
            uint2 v = *(const uint2*)(g_hh + (size_t)s * K2 + lane * 2);
            float2 f0 = bf16_unpack2(v.x);
            float2 f1 = bf16_unpack2(v.y);
            acc.x += nw * f0.x;
            acc.y += nw * f0.y;
            acc.z += nw * f1.x;
            acc.w += nw * f1.y;
        }
    }
    int c = lane * 4;
    float4 G  = *(const float4*)(gg + c);
    float4 BE = *(const float4*)(be + c);
    float4 M  = *(const float4*)(mm + c);
    float4 V  = *(const float4*)(vv + c);
    float r;
    r = (acc.x - M.x) * (G.x * rsqrtf(V.x + BN_EPS)) + BE.x; acc.x = fmaxf(r, 0.f);
    r = (acc.y - M.y) * (G.y * rsqrtf(V.y + BN_EPS)) + BE.y; acc.y = fmaxf(r, 0.f);
    r = (acc.z - M.z) * (G.z * rsqrtf(V.z + BN_EPS)) + BE.z; acc.z = fmaxf(r, 0.f);
    r = (acc.w - M.w) * (G.w * rsqrtf(V.w + BN_EPS)) + BE.w; acc.w = fmaxf(r, 0.f);
    uint2 hi, lo;
    hi.x = bf16_split2(acc.x, acc.y, lo.x);
    hi.y = bf16_split2(acc.z, acc.w, lo.y);
    *(uint2*)(g_ah + ri) = hi;
    *(uint2*)(g_al + ri) = lo;
}

// -------- last layer: aggregation (d=40, fp32 g_h) + fused log_softmax ------
__global__ void k_agg40(float* __restrict__ out) {
    int w    = (blockIdx.x * blockDim.x + threadIdx.x) >> 5;
    int lane = threadIdx.x & 31;
    if (w >= NN) return;
    const float* __restrict__ h = (const float*)g_h;
    float di = g_dinv[w];
    float sn = di * di;
    const float* hr = h + (size_t)w * DO;
    float a0 = sn * hr[lane];
    float a1 = (lane < 8) ? sn * hr[32 + lane] : 0.f;
    int e0 = g_start[w], e1 = g_start[w + 1];
    for (int eb = e0; eb < e1; eb += 32) {
        int n = e1 - eb;
        if (n > 32) n = 32;
        int   si = 0;
        float dv = 0.f;
        if (lane < n) {
            si = g_srcCSR[eb + lane];
            dv = g_dinv[si];
        }
        for (int j = 0; j < n; j++) {
            int   s  = __shfl_sync(0xffffffffu, si, j);
            float nw = __shfl_sync(0xffffffffu, dv, j) * di;
            const float* hs = h + (size_t)s * DO;
            a0 += nw * hs[lane];
            if (lane < 8) a1 += nw * hs[32 + lane];
        }
    }
    float mx = a0;
    if (lane < 8) mx = fmaxf(mx, a1);
#pragma unroll
    for (int off = 16; off > 0; off >>= 1)
        mx = fmaxf(mx, __shfl_xor_sync(0xffffffffu, mx, off));
    float se = expf(a0 - mx) + ((lane < 8) ? expf(a1 - mx) : 0.f);
#pragma unroll
    for (int off = 16; off > 0; off >>= 1)
        se += __shfl_xor_sync(0xffffffffu, se, off);
    float lse = mx + logf(se);
    out[(size_t)w * DO + lane] = a0 - lse;
    if (lane < 8) out[(size_t)w * DO + 32 + lane] = a1 - lse;
}

// ---------------- launch ----------------------------------------------------
extern "C" void kernel_launch(void* const* d_in, const int* in_sizes, int n_in,
                              void* d_out, int out_size) {
    const float* x  = (const float*)d_in[0];
    const void*  ei = d_in[1];
    const float* W0 = (const float*)d_in[2];
    const float* b0 = (const float*)d_in[3];
    const float* W1 = (const float*)d_in[4];
    const float* b1 = (const float*)d_in[5];
    const float* W2 = (const float*)d_in[6];
    const float* b2 = (const float*)d_in[7];
    const float* g0  = (const float*)d_in[8];
    const float* be0 = (const float*)d_in[9];
    const float* m0  = (const float*)d_in[10];
    const float* v0  = (const float*)d_in[11];
    const float* g1  = (const float*)d_in[12];
    const float* be1 = (const float*)d_in[13];
    const float* m1  = (const float*)d_in[14];
    const float* v1  = (const float*)d_in[15];
    float* out = (float*)d_out;

    const int TB = 256;
    int gbN = (NN + TB - 1) / TB;
    int gbE = (EE + TB - 1) / TB;
    int gbGemm = (NN + 127) / 128;
    int gbWarp = (NN + (TB / 32) - 1) / (TB / 32);
    int gbSplit = ((NN * DH / 8) + TB - 1) / TB;

    cudaStream_t s2;
    cudaStreamCreate(&s2);
    cudaEvent_t eFork, eJoin;
    cudaEventCreateWithFlags(&eFork, cudaEventDisableTiming);
    cudaEventCreateWithFlags(&eJoin, cudaEventDisableTiming);

    cudaEventRecord(eFork, 0);
    cudaStreamWaitEvent(s2, eFork, 0);

    // k_gemm_tc<0> kept as 4th submission (profiled by ncu).
    k_split<<<gbSplit, TB>>>(x, W0, W1);          // 1 (main)
    k_zero<<<gbN, TB, 0, s2>>>((const int*)ei);   // 2 (s2)
    k_count<<<gbE, TB, 0, s2>>>(ei);              // 3 (s2)
    k_gemm_tc<0><<<gbGemm, TB>>>(b0);             // 4 (main)  <- profiled
    k_scan1<<<SCAN_B, 1024, 0, s2>>>();           // 5 (s2)
    k_scan23<<<gbN, TB, 0, s2>>>();               // 6 (s2)
    k_fill<<<gbE, TB, 0, s2>>>(ei);               // 7 (s2)
    cudaEventRecord(eJoin, s2);
    cudaStreamWaitEvent(0, eJoin, 0);

    k_agg128<<<gbWarp, TB>>>(g0, be0, m0, v0);    // g_hh -> g_ah/g_al
    k_gemm_tc<1><<<gbGemm, TB>>>(b1);             // g_ah -> g_hh (bf16)
    k_agg128<<<gbWarp, TB>>>(g1, be1, m1, v1);    // g_hh -> g_ah/g_al
    k_gemm40<<<gbGemm, 160>>>(W2, b2);            // -> g_h (fp32, 40-wide)
    k_agg40<<<gbWarp, TB>>>(out);                 // g_h -> out
}